// round 17
// baseline (speedup 1.0000x reference)
#include <cuda_runtime.h>

// StackedLSTM: B=2048, T=2048, D=H=6, 2 layers, softmax over final h of layer 1.
// 16 lanes/batch (lanes 0-7 layer 0 unit j, lanes 8-15 layer 1), 2 warps/SMSP.
// Unified 16-record smem ring per group; record = 96B {x[6]|h0[6]|h1[6]}, all
// fields 16B aligned. x bulk-staged into the ring (8 steps at a time), so the
// per-iteration input read is one vector-LDS pair with a per-lane base pointer
// (L0 -> x field, L1 -> h0 field): no SELs, no x register buffers. All ring
// addresses are compile-time immediates off 7 preset pointers (16x unroll);
// ring wrap at offsets 0/1 handled by +1536 shadow pointers. R6 k-pair f32x2
// math with prescaled sigmoid, one group-masked syncwarp per iteration.

#define TT 2048
#define REC 96          // record stride bytes
#define GRP 1536        // group region = 16 records
#define XBYTES (TT * 24)

typedef unsigned long long u64;
typedef ulonglong2 u64x2;

static __device__ __forceinline__ u64 pack2(float lo, float hi) {
    u64 r; asm("mov.b64 %0, {%1, %2};" : "=l"(r) : "f"(lo), "f"(hi)); return r;
}
static __device__ __forceinline__ void unpack2(u64 v, float& lo, float& hi) {
    asm("mov.b64 {%0, %1}, %2;" : "=f"(lo), "=f"(hi) : "l"(v));
}
static __device__ __forceinline__ u64 ffma2(u64 a, u64 b, u64 c) {
    u64 d; asm("fma.rn.f32x2 %0, %1, %2, %3;" : "=l"(d) : "l"(a), "l"(b), "l"(c));
    return d;
}
static __device__ __forceinline__ u64 fadd2(u64 a, u64 b) {
    u64 d; asm("add.rn.f32x2 %0, %1, %2;" : "=l"(d) : "l"(a), "l"(b)); return d;
}
static __device__ __forceinline__ float tanh_f(float x) {
    float y; asm("tanh.approx.f32 %0, %1;" : "=f"(y) : "f"(x)); return y;
}

struct CellW {
    u64 wx[4][3];   // input-side k-pair weights per gate (i,f,g,o), prescaled
    u64 wh[4][3];   // recurrent-side k-pair weights
    u64 b[4];       // {prescaled bias, 0}
};

// Proven R6 cell: in[3]/rg[3] are k-pair packed {v2k,v2k+1} vectors.
static __device__ __forceinline__ void cell(const CellW& W, const u64* in, const u64* rg,
                                            float& h, float& c) {
    float g[4];
#pragma unroll
    for (int q = 0; q < 4; ++q) {
        u64 ax = ffma2(W.wx[q][0], in[0], W.b[q]);
        ax     = ffma2(W.wx[q][1], in[1], ax);
        ax     = ffma2(W.wx[q][2], in[2], ax);
        u64 ah = ffma2(W.wh[q][0], rg[0], 0ull);
        ah     = ffma2(W.wh[q][1], rg[1], ah);
        ah     = ffma2(W.wh[q][2], rg[2], ah);
        u64 s2 = fadd2(ax, ah);
        float lo, hi; unpack2(s2, lo, hi);
        g[q] = lo + hi;
    }
    float gi = fmaf(tanh_f(g[0]), 0.5f, 0.5f);
    float gf = fmaf(tanh_f(g[1]), 0.5f, 0.5f);
    float gg = tanh_f(g[2]);
    float go = fmaf(tanh_f(g[3]), 0.5f, 0.5f);
    c = fmaf(gf, c, gi * gg);
    h = go * tanh_f(c);
}

struct Ctx {
    const char *pin, *pin_w;            // input read base (x | rec[n-1].h0)
    const char *prec, *prec_w0, *prec_w1; // recurrent read base
    char *pw, *pw_w;                    // h write base
    unsigned gmask;
    bool isL1;
};

// One iteration at compile-time ring offset OFF (= n mod 16).
template <int OFF, bool ZF>
static __device__ __forceinline__ void iter(const CellW& W, const Ctx& C,
                                            float& h, float& c) {
    const char* bin = ((OFF == 0) ? C.pin_w : C.pin) + REC * OFF;
    const char* brc = ((OFF == 0) ? C.prec_w0 : (OFF == 1) ? C.prec_w1 : C.prec)
                      + REC * OFF;
    char* bw = ((OFF == 0) ? C.pw_w : C.pw) + REC * OFF;

    __syncwarp(C.gmask);
    u64x2 iA = *(const u64x2*)bin;  u64 iB = *(const u64*)(bin + 16);
    u64x2 rA = *(const u64x2*)brc;  u64 rB = *(const u64*)(brc + 16);
    u64 in[3] = { iA.x, iA.y, iB };
    u64 rg[3] = { rA.x, rA.y, rB };
    cell(W, in, rg, h, c);
    if (ZF && C.isL1) { h = 0.f; c = 0.f; }   // n=0: layer-1 step is spurious
    *(float*)bw = h;
}

// Stage 8 timesteps of x (steps bt..bt+7, 192B) into the ring's x fields.
// hoff = 0 (records 0..7) or 768 (records 8..15). Lanes 0..11 active.
static __device__ __forceinline__ void stage(const char* __restrict__ xb,
                                             char* const* sA, int l16,
                                             int bt, int hoff) {
    if (l16 < 12) {
        int off = 24 * bt + 16 * l16;
        if (off > XBYTES - 16) off = XBYTES - 16;   // clamp: junk data only
        float4 v = *(const float4*)(xb + off);
        *(float*)(sA[0] + hoff) = v.x;
        *(float*)(sA[1] + hoff) = v.y;
        *(float*)(sA[2] + hoff) = v.z;
        *(float*)(sA[3] + hoff) = v.w;
    }
}

__global__ void __launch_bounds__(256, 1)
stacked_lstm_kernel(const float* __restrict__ x,
                    const float* __restrict__ Wi0, const float* __restrict__ Wh0,
                    const float* __restrict__ bi0, const float* __restrict__ bh0,
                    const float* __restrict__ Wi1, const float* __restrict__ Wh1,
                    const float* __restrict__ bi1, const float* __restrict__ bh1,
                    float* __restrict__ out) {
    const int l16   = threadIdx.x & 15;
    const bool isL1 = (l16 & 8) != 0;
    const int j     = l16 & 7;
    const int jj    = (j < 6) ? j : 5;       // clamp for idle lanes 6,7
    const int wg    = threadIdx.x >> 4;      // group in block (0..15)
    const int b     = (blockIdx.x * blockDim.x + threadIdx.x) >> 4;

    const float* Wi = isL1 ? Wi1 : Wi0;
    const float* Wh = isL1 ? Wh1 : Wh0;
    const float* bi = isL1 ? bi1 : bi0;
    const float* bh = isL1 ? bh1 : bh0;

    // PyTorch gate rows: i=[0:6) f=[6:12) g=[12:18) o=[18:24).
    // Sigmoid gates (i,f,o) prescaled by 0.5: sig = .5 + .5*tanh(prescaled).
    CellW W;
    const int   goff[4] = {0, 6, 12, 18};
    const float gscl[4] = {0.5f, 0.5f, 1.0f, 0.5f};
#pragma unroll
    for (int q = 0; q < 4; ++q) {
        const int   r = goff[q] + jj;
        const float s = gscl[q];
#pragma unroll
        for (int p = 0; p < 3; ++p) {
            W.wx[q][p] = pack2(s * Wi[r * 6 + 2 * p], s * Wi[r * 6 + 2 * p + 1]);
            W.wh[q][p] = pack2(s * Wh[r * 6 + 2 * p], s * Wh[r * 6 + 2 * p + 1]);
        }
        W.b[q] = pack2(s * (bi[r] + bh[r]), 0.f);
    }

    // Ring: 16 groups x 16 records x 96B. Record: x@0, pad@24, h0@32, pad@56,
    // h1@64, pad@88. Idle lanes (j=6,7) write into the pads.
    __shared__ __align__(16) char sbuf[16 * GRP];
    char* G = sbuf + wg * GRP;

    Ctx C;
    C.gmask  = 0xFFFFu << (threadIdx.x & 16);
    C.isL1   = isL1;
    C.pin    = isL1 ? G - 64 : G;            // rec[n-1].h0 | rec[n].x
    C.pin_w  = isL1 ? G - 64 + GRP : G;
    C.prec   = isL1 ? G - 128 : G - 64;      // rec[n-2].h1 | rec[n-1].h0
    C.prec_w0 = C.prec + GRP;                // both roles wrap at OFF 0
    C.prec_w1 = isL1 ? C.prec + GRP : C.prec;  // only L1 wraps at OFF 1
    C.pw     = (isL1 ? G - 32 : G + 32) + 4 * j;
    C.pw_w   = isL1 ? C.pw + GRP : C.pw;

    // Staging addresses: lane l16<12 stores float f=4*l16+i of an 8-step block
    // into record f/6, x-position f%6.
    char* sA[4];
#pragma unroll
    for (int i = 0; i < 4; ++i) {
        int f = 4 * l16 + i;
        sA[i] = G + REC * (f / 6) + 4 * (f % 6);
    }

    const char* xb = (const char*)(x + (size_t)b * TT * 6);

    // Zero the group region (h fields must start 0; x gets staged over).
#pragma unroll
    for (int k = 0; k < 6; ++k)
        *(float4*)(G + 16 * l16 + 256 * k) = make_float4(0.f, 0.f, 0.f, 0.f);
    __syncwarp();

    // Prologue: stage steps 0..15.
    stage(xb, sA, l16, 0, 0);
    stage(xb, sA, l16, 8, 768);

    float h = 0.f, c = 0.f;

    // Body 0: n = 0..15 (ZF at n=0).
    iter<0, true >(W, C, h, c);
    iter<1, false>(W, C, h, c);
    iter<2, false>(W, C, h, c);
    iter<3, false>(W, C, h, c);
    iter<4, false>(W, C, h, c);
    iter<5, false>(W, C, h, c);
    iter<6, false>(W, C, h, c);
    iter<7, false>(W, C, h, c);
    stage(xb, sA, l16, 16, 0);
    iter<8,  false>(W, C, h, c);
    iter<9,  false>(W, C, h, c);
    iter<10, false>(W, C, h, c);
    iter<11, false>(W, C, h, c);
    iter<12, false>(W, C, h, c);
    iter<13, false>(W, C, h, c);
    iter<14, false>(W, C, h, c);
    iter<15, false>(W, C, h, c);
    stage(xb, sA, l16, 24, 768);

    // Bodies 1..127: n = 16k .. 16k+15; staging prefetches steps 16(k+1)..+15.
#pragma unroll 1
    for (int k = 1; k < 128; ++k) {
        iter<0, false>(W, C, h, c);
        iter<1, false>(W, C, h, c);
        iter<2, false>(W, C, h, c);
        iter<3, false>(W, C, h, c);
        iter<4, false>(W, C, h, c);
        iter<5, false>(W, C, h, c);
        iter<6, false>(W, C, h, c);
        iter<7, false>(W, C, h, c);
        stage(xb, sA, l16, 16 * k + 16, 0);
        iter<8,  false>(W, C, h, c);
        iter<9,  false>(W, C, h, c);
        iter<10, false>(W, C, h, c);
        iter<11, false>(W, C, h, c);
        iter<12, false>(W, C, h, c);
        iter<13, false>(W, C, h, c);
        iter<14, false>(W, C, h, c);
        iter<15, false>(W, C, h, c);
        stage(xb, sA, l16, 16 * k + 24, 768);
    }

    // Epilogue n=2048 (OFF 0): L1 computes t=2047 (input rec[15].h0 = h0(2047),
    // recurrent rec[14].h1 = h1(2046) via wrap pointers); L0 computes junk.
    iter<0, false>(W, C, h, c);

    // Final exchange: L1 lanes' registers hold h1(2047). Scratch in rec[0].
    __syncwarp(C.gmask);
    *(float*)(G + 4 * j + (isL1 ? 0 : 32)) = h;
    __syncwarp(C.gmask);
    {
        float hv[6];
#pragma unroll
        for (int k = 0; k < 6; ++k) hv[k] = *(const float*)(G + 4 * k);
        float mx = hv[0];
#pragma unroll
        for (int k = 1; k < 6; ++k) mx = fmaxf(mx, hv[k]);
        float sum = 0.f, ev[6];
#pragma unroll
        for (int k = 0; k < 6; ++k) { ev[k] = __expf(hv[k] - mx); sum += ev[k]; }
        if (isL1 && j < 6)
            out[(size_t)b * 6 + j] = __fdividef(ev[j], sum);
    }
}

extern "C" void kernel_launch(void* const* d_in, const int* in_sizes, int n_in,
                              void* d_out, int out_size) {
    (void)in_sizes; (void)n_in; (void)out_size;
    const float* x   = (const float*)d_in[0];
    const float* Wi0 = (const float*)d_in[1];
    const float* Wh0 = (const float*)d_in[2];
    const float* bi0 = (const float*)d_in[3];
    const float* bh0 = (const float*)d_in[4];
    const float* Wi1 = (const float*)d_in[5];
    const float* Wh1 = (const float*)d_in[6];
    const float* bi1 = (const float*)d_in[7];
    const float* bh1 = (const float*)d_in[8];
    float* out = (float*)d_out;

    // 2048 batches * 16 lanes = 32768 threads = 128 blocks x 256 threads:
    // 1 block/SM on 128 SMs, 2 warps/SMSP (the proven best residency).
    stacked_lstm_kernel<<<128, 256>>>(x, Wi0, Wh0, bi0, bh0, Wi1, Wh1, bi1, bh1, out);
}